// round 1
// baseline (speedup 1.0000x reference)
#include <cuda_runtime.h>

// Row-wise softmax (no max subtraction, matching reference):
//   y = exp(x) / sum(exp(x), axis=-1)
// x: (16384, 4096) fp32.  One CTA per row, 256 threads, 16 elems/thread in
// registers (4x float4). Single read + single write per element (HBM-bound
// minimum traffic: 512 MiB).

#ifndef ROWS
#define ROWS 16384
#endif
#define COLS 4096
#define THREADS 256
#define VECS_PER_THREAD 4   // 4 float4 = 16 floats; 256*16 = 4096

__global__ __launch_bounds__(THREADS, 8)
void softmax_row_kernel(const float4* __restrict__ x, float4* __restrict__ y) {
    const int row = blockIdx.x;
    const size_t base = (size_t)row * (COLS / 4);
    const float4* xr = x + base;
    float4* yr = y + base;
    const int tid = threadIdx.x;

    float4 v[VECS_PER_THREAD];
    float local = 0.0f;

    // Front-batched vector loads (MLP=4), exp on the fly, keep in registers.
#pragma unroll
    for (int i = 0; i < VECS_PER_THREAD; ++i) {
        float4 t = xr[tid + i * THREADS];
        t.x = __expf(t.x);
        t.y = __expf(t.y);
        t.z = __expf(t.z);
        t.w = __expf(t.w);
        local += (t.x + t.y) + (t.z + t.w);
        v[i] = t;
    }

    // Block reduction: warp shuffle then cross-warp via smem broadcast.
    __shared__ float warp_sums[THREADS / 32];
#pragma unroll
    for (int o = 16; o > 0; o >>= 1)
        local += __shfl_xor_sync(0xFFFFFFFFu, local, o);
    if ((tid & 31) == 0)
        warp_sums[tid >> 5] = local;
    __syncthreads();

    float total = 0.0f;
#pragma unroll
    for (int w = 0; w < THREADS / 32; ++w)
        total += warp_sums[w];  // broadcast LDS, conflict-free

    const float inv = 1.0f / total;

#pragma unroll
    for (int i = 0; i < VECS_PER_THREAD; ++i) {
        float4 t = v[i];
        t.x *= inv;
        t.y *= inv;
        t.z *= inv;
        t.w *= inv;
        yr[tid + i * THREADS] = t;
    }
}

extern "C" void kernel_launch(void* const* d_in, const int* in_sizes, int n_in,
                              void* d_out, int out_size) {
    const float4* x = (const float4*)d_in[0];
    float4* y = (float4*)d_out;
    const int rows = in_sizes[0] / COLS;  // 16384
    softmax_row_kernel<<<rows, THREADS>>>(x, y);
}

// round 2
// speedup vs baseline: 1.0008x; 1.0008x over previous
#include <cuda_runtime.h>

// Row-wise softmax (no max subtraction, matching reference):
//   y = exp(x) / sum(exp(x), axis=-1)
// x: (16384, 4096) fp32.  One CTA per row, 128 threads, 32 elems/thread
// (8x float4) in registers. Streaming cache hints (.cs) on both sides.
// Minimum traffic: 1 read + 1 write per element = 512 MiB total.

#define COLS 4096
#define THREADS 128
#define VECS_PER_THREAD 8   // 8 float4 = 32 floats; 128*32 = 4096

__device__ __forceinline__ float4 ldcs4(const float4* p) {
    float4 v;
    asm volatile("ld.global.cs.v4.f32 {%0,%1,%2,%3}, [%4];"
                 : "=f"(v.x), "=f"(v.y), "=f"(v.z), "=f"(v.w)
                 : "l"(p));
    return v;
}

__device__ __forceinline__ void stcs4(float4* p, float4 v) {
    asm volatile("st.global.cs.v4.f32 [%0], {%1,%2,%3,%4};"
                 :: "l"(p), "f"(v.x), "f"(v.y), "f"(v.z), "f"(v.w));
}

__global__ __launch_bounds__(THREADS, 8)
void softmax_row_kernel(const float4* __restrict__ x, float4* __restrict__ y) {
    const int row = blockIdx.x;
    const size_t base = (size_t)row * (COLS / 4);
    const float4* xr = x + base;
    float4* yr = y + base;
    const int tid = threadIdx.x;

    float4 v[VECS_PER_THREAD];

    // Front-batched vector loads (MLP_p1 = 8), streaming.
#pragma unroll
    for (int i = 0; i < VECS_PER_THREAD; ++i)
        v[i] = ldcs4(xr + tid + i * THREADS);

    // exp + local sum in registers.
    float local = 0.0f;
#pragma unroll
    for (int i = 0; i < VECS_PER_THREAD; ++i) {
        v[i].x = __expf(v[i].x);
        v[i].y = __expf(v[i].y);
        v[i].z = __expf(v[i].z);
        v[i].w = __expf(v[i].w);
        local += (v[i].x + v[i].y) + (v[i].z + v[i].w);
    }

    // Block reduction: warp shuffle, then 4 warp sums via smem broadcast.
    __shared__ float warp_sums[THREADS / 32];
#pragma unroll
    for (int o = 16; o > 0; o >>= 1)
        local += __shfl_xor_sync(0xFFFFFFFFu, local, o);
    if ((tid & 31) == 0)
        warp_sums[tid >> 5] = local;
    __syncthreads();

    float total = (warp_sums[0] + warp_sums[1]) + (warp_sums[2] + warp_sums[3]);
    const float inv = 1.0f / total;

#pragma unroll
    for (int i = 0; i < VECS_PER_THREAD; ++i) {
        float4 t = v[i];
        t.x *= inv;
        t.y *= inv;
        t.z *= inv;
        t.w *= inv;
        stcs4(yr + tid + i * THREADS, t);
    }
}

extern "C" void kernel_launch(void* const* d_in, const int* in_sizes, int n_in,
                              void* d_out, int out_size) {
    const float4* x = (const float4*)d_in[0];
    float4* y = (float4*)d_out;
    const int rows = in_sizes[0] / COLS;  // 16384
    softmax_row_kernel<<<rows, THREADS>>>(x, y);
}